// round 2
// baseline (speedup 1.0000x reference)
#include <cuda_runtime.h>
#include <cuda_fp16.h>
#include <cstdint>

// ---------------- problem constants ----------------
#define INDIM 4096
#define NGRP  16
#define KROOT 2048
#define NOUT  256

// ---------------- device scratch (no cudaMalloc allowed) ----------------
__device__ __half g_Wm[NGRP][128][256];     // folded mid weights [g][n][k], fp16
__device__ float  g_cmid[NGRP][128];        // folded constants
__device__ __half g_Wr[NOUT][KROOT];        // root weights [n][k], fp16
__device__ __half g_midh[16384][KROOT];     // mid activations, hi fp16
__device__ __half g_midl[16384][KROOT];     // mid activations, lo fp16 (residual)

// ---------------- helpers ----------------
__device__ __forceinline__ unsigned smem_u32(const void* p) {
    unsigned a;
    asm("{ .reg .u64 t; cvta.to.shared.u64 t, %1; cvt.u32.u64 %0, t; }" : "=r"(a) : "l"(p));
    return a;
}
__device__ __forceinline__ void cp_async16(unsigned s, const void* g) {
    asm volatile("cp.async.cg.shared.global [%0], [%1], 16;" :: "r"(s), "l"(g));
}
#define CP_COMMIT() asm volatile("cp.async.commit_group;")
#define CP_WAIT0()  asm volatile("cp.async.wait_group 0;")
#define CP_WAIT1()  asm volatile("cp.async.wait_group 1;")

__device__ __forceinline__ void ldsm4(unsigned& r0, unsigned& r1, unsigned& r2, unsigned& r3,
                                      unsigned addr) {
    asm volatile("ldmatrix.sync.aligned.m8n8.x4.shared.b16 {%0,%1,%2,%3}, [%4];"
                 : "=r"(r0), "=r"(r1), "=r"(r2), "=r"(r3) : "r"(addr));
}
__device__ __forceinline__ void mma16816(float* c, const unsigned* a, unsigned b0, unsigned b1) {
    asm volatile(
        "mma.sync.aligned.m16n8k16.row.col.f32.f16.f16.f32 "
        "{%0,%1,%2,%3},{%4,%5,%6,%7},{%8,%9},{%0,%1,%2,%3};"
        : "+f"(c[0]), "+f"(c[1]), "+f"(c[2]), "+f"(c[3])
        : "r"(a[0]), "r"(a[1]), "r"(a[2]), "r"(a[3]), "r"(b0), "r"(b1));
}
__device__ __forceinline__ float fast_tanh(float v) {
    v = fminf(fmaxf(v, -15.f), 15.f);
    float e = __expf(2.f * v);
    return __fdividef(e - 1.f, e + 1.f);
}
__device__ __forceinline__ unsigned packhl(float v) {
    __half h = __float2half_rn(v);
    __half l = __float2half_rn(v - __half2float(h));
    return (unsigned)__half_as_ushort(h) | ((unsigned)__half_as_ushort(l) << 16);
}
__device__ __forceinline__ unsigned packf2(float lo, float hi) {
    __half2 h = __floats2half2_rn(lo, hi);
    return *(unsigned*)&h;
}

// ---------------- prep ----------------
__global__ void k_prep_mid(const float* __restrict__ w_inp, const float* __restrict__ pbias,
                           const float* __restrict__ W_mid, const float* __restrict__ b_mid) {
    int g = blockIdx.x >> 7, n = blockIdx.x & 127, j = threadIdx.x;
    float wm = W_mid[(g * 256 + j) * 128 + n];
    g_Wm[g][n][j] = __float2half_rn(w_inp[g * 256 + j] * wm);
    __shared__ float red[256];
    red[j] = pbias[(g * 256 + j) >> 6] * wm;
    __syncthreads();
    for (int s = 128; s > 0; s >>= 1) {
        if (j < s) red[j] += red[j + s];
        __syncthreads();
    }
    if (j == 0) g_cmid[g][n] = red[0] + b_mid[g * 128 + n];
}
__global__ void k_prep_root(const float* __restrict__ W_root) {
    int idx = blockIdx.x * 256 + threadIdx.x;
    int k = idx >> 8, n = idx & 255;
    g_Wr[n][k] = __float2half_rn(W_root[idx]);
}

// ================= MID: [128b x 128n] per CTA, K=256, fp16 single-pass =================
// smem per buf: A32[128][68] f32 (34816 B) + B[128][72] half (18432 B) = 53248; x2 = 106496
#define MID_ASTR 68
#define MID_BSTR 72
#define MID_BUF  53248u
#define MID_SMEM 106496

__global__ void __launch_bounds__(256, 1) k_mid(const float* __restrict__ x) {
    extern __shared__ char smem[];
    unsigned sb = smem_u32(smem);
    const int tid = threadIdx.x, lane = tid & 31, wid = tid >> 5;
    const int wm = wid & 3, wn = wid >> 2;            // 4 M-warps x 2 N-warps
    const long long b0 = (long long)blockIdx.x * 128;
    const int g = blockIdx.y;

    float acc[2][8][4];
#pragma unroll
    for (int i = 0; i < 2; i++)
#pragma unroll
        for (int j = 0; j < 8; j++)
#pragma unroll
            for (int q = 0; q < 4; q++) acc[i][j][q] = 0.f;

#define MID_LOAD(CH, BUF)                                                            \
    do {                                                                             \
        unsigned A = sb + (BUF) * MID_BUF, B = A + 34816u;                           \
        int k0 = (CH) * 64;                                                          \
        _Pragma("unroll") for (int j = 0; j < 8; j++) {                              \
            int idx = tid + j * 256;                                                 \
            int r = idx >> 4, c4 = idx & 15;                                         \
            cp_async16(A + (unsigned)(r * MID_ASTR + c4 * 4) * 4u,                   \
                       x + (b0 + r) * INDIM + g * 256 + k0 + c4 * 4);                \
        }                                                                            \
        _Pragma("unroll") for (int j = 0; j < 4; j++) {                              \
            int idx = tid + j * 256;                                                 \
            int n = idx >> 3, c8 = idx & 7;                                          \
            cp_async16(B + (unsigned)(n * MID_BSTR + c8 * 8) * 2u,                   \
                       &g_Wm[g][n][k0 + c8 * 8]);                                    \
        }                                                                            \
    } while (0)

    MID_LOAD(0, 0);
    CP_COMMIT();
    for (int ch = 0; ch < 4; ch++) {
        if (ch < 3) {
            MID_LOAD(ch + 1, (ch + 1) & 1);
            CP_COMMIT();
            CP_WAIT1();
        } else {
            CP_WAIT0();
        }
        __syncthreads();
        const float* A32 = (const float*)(smem + (ch & 1) * MID_BUF);
        unsigned B = sb + (ch & 1) * MID_BUF + 34816u;
#pragma unroll
        for (int ks = 0; ks < 4; ks++) {
            int k0 = ks * 16;
            unsigned bfr[8][2];
#pragma unroll
            for (int p = 0; p < 4; p++) {
                int grp = lane >> 3, r = lane & 7;
                int n = wn * 64 + p * 16 + ((grp >> 1) << 3) + r;
                int kk = k0 + ((grp & 1) << 3);
                unsigned q0, q1, q2, q3;
                ldsm4(q0, q1, q2, q3, B + (unsigned)(n * MID_BSTR + kk) * 2u);
                bfr[2 * p][0] = q0; bfr[2 * p][1] = q1;
                bfr[2 * p + 1][0] = q2; bfr[2 * p + 1][1] = q3;
            }
            unsigned afr[2][4];
#pragma unroll
            for (int mt = 0; mt < 2; mt++) {
                int row = wm * 32 + mt * 16 + (lane >> 2);
                int c = k0 + ((lane & 3) << 1);
                float2 v0 = *(const float2*)(A32 + row * MID_ASTR + c);
                float2 v1 = *(const float2*)(A32 + (row + 8) * MID_ASTR + c);
                float2 v2 = *(const float2*)(A32 + row * MID_ASTR + c + 8);
                float2 v3 = *(const float2*)(A32 + (row + 8) * MID_ASTR + c + 8);
                afr[mt][0] = packf2(v0.x, v0.y);
                afr[mt][1] = packf2(v1.x, v1.y);
                afr[mt][2] = packf2(v2.x, v2.y);
                afr[mt][3] = packf2(v3.x, v3.y);
            }
#pragma unroll
            for (int mt = 0; mt < 2; mt++)
#pragma unroll
                for (int nt = 0; nt < 8; nt++)
                    mma16816(acc[mt][nt], afr[mt], bfr[nt][0], bfr[nt][1]);
        }
        __syncthreads();
    }

    // epilogue: +c, tanh, fp16 hi/lo split, smem transpose, wide coalesced stores
    unsigned* trans = (unsigned*)smem;   // [128][132] u32
#pragma unroll
    for (int mt = 0; mt < 2; mt++)
#pragma unroll
        for (int nt = 0; nt < 8; nt++) {
            int bl = wm * 32 + mt * 16 + (lane >> 2);
            int n = wn * 64 + nt * 8 + ((lane & 3) << 1);
            float c0 = fast_tanh(acc[mt][nt][0] + g_cmid[g][n]);
            float c1 = fast_tanh(acc[mt][nt][1] + g_cmid[g][n + 1]);
            float c2 = fast_tanh(acc[mt][nt][2] + g_cmid[g][n]);
            float c3 = fast_tanh(acc[mt][nt][3] + g_cmid[g][n + 1]);
            *(uint2*)&trans[bl * 132 + n] = make_uint2(packhl(c0), packhl(c1));
            *(uint2*)&trans[(bl + 8) * 132 + n] = make_uint2(packhl(c2), packhl(c3));
        }
    __syncthreads();
#pragma unroll
    for (int j = 0; j < 16; j++) {
        int f4 = tid + j * 256;         // uint4 index over [128][32]
        int b = f4 >> 5, n4 = f4 & 31;
        uint4 v = *(uint4*)&trans[b * 132 + n4 * 4];
        unsigned h01 = (v.x & 0xffffu) | (v.y << 16);
        unsigned h23 = (v.z & 0xffffu) | (v.w << 16);
        unsigned l01 = (v.x >> 16) | (v.y & 0xffff0000u);
        unsigned l23 = (v.z >> 16) | (v.w & 0xffff0000u);
        long long row = b0 + b;
        *(uint2*)&g_midh[row][g * 128 + n4 * 4] = make_uint2(h01, h23);
        *(uint2*)&g_midl[row][g * 128 + n4 * 4] = make_uint2(l01, l23);
    }
}

// ================= ROOT: [128b x 256n] per CTA, K=2048, 2-pass fp16 split =================
// smem per buf: Ah[128][72]h (18432) + Al (18432) + B[256][72]h (36864) = 73728; x2 = 147456
#define RT_STR  72
#define RT_BUF  73728u
#define RT_SMEM 147456

__global__ void __launch_bounds__(512, 1) k_root(float* __restrict__ out,
                                                 const float* __restrict__ b_root) {
    extern __shared__ char smem[];
    unsigned sb = smem_u32(smem);
    const int tid = threadIdx.x, lane = tid & 31, wid = tid >> 5;
    const int wm = wid & 3, wn = wid >> 2;            // 4 M-warps x 4 N-warps
    const long long b0 = (long long)blockIdx.x * 128;

    float acc[2][8][4];
#pragma unroll
    for (int i = 0; i < 2; i++)
#pragma unroll
        for (int j = 0; j < 8; j++)
#pragma unroll
            for (int q = 0; q < 4; q++) acc[i][j][q] = 0.f;

#define RT_LOAD(CH, BUF)                                                             \
    do {                                                                             \
        unsigned Ah = sb + (BUF) * RT_BUF, Al = Ah + 18432u, B = Ah + 36864u;        \
        int k0 = (CH) * 64;                                                          \
        _Pragma("unroll") for (int j = 0; j < 2; j++) {                              \
            int idx = tid + j * 512;                                                 \
            int r = idx >> 3, c8 = idx & 7;                                          \
            unsigned so = (unsigned)(r * RT_STR + c8 * 8) * 2u;                      \
            cp_async16(Ah + so, &g_midh[b0 + r][k0 + c8 * 8]);                       \
            cp_async16(Al + so, &g_midl[b0 + r][k0 + c8 * 8]);                       \
        }                                                                            \
        _Pragma("unroll") for (int j = 0; j < 4; j++) {                              \
            int idx = tid + j * 512;                                                 \
            int n = idx >> 3, c8 = idx & 7;                                          \
            cp_async16(B + (unsigned)(n * RT_STR + c8 * 8) * 2u,                     \
                       &g_Wr[n][k0 + c8 * 8]);                                       \
        }                                                                            \
    } while (0)

    RT_LOAD(0, 0);
    CP_COMMIT();
    for (int ch = 0; ch < 32; ch++) {
        if (ch < 31) {
            RT_LOAD(ch + 1, (ch + 1) & 1);
            CP_COMMIT();
            CP_WAIT1();
        } else {
            CP_WAIT0();
        }
        __syncthreads();
        unsigned Ah = sb + (ch & 1) * RT_BUF, Al = Ah + 18432u, B = Ah + 36864u;
#pragma unroll
        for (int ks = 0; ks < 4; ks++) {
            int k0 = ks * 16;
            unsigned bfr[8][2];
#pragma unroll
            for (int p = 0; p < 4; p++) {
                int grp = lane >> 3, r = lane & 7;
                int n = wn * 64 + p * 16 + ((grp >> 1) << 3) + r;
                int kk = k0 + ((grp & 1) << 3);
                unsigned q0, q1, q2, q3;
                ldsm4(q0, q1, q2, q3, B + (unsigned)(n * RT_STR + kk) * 2u);
                bfr[2 * p][0] = q0; bfr[2 * p][1] = q1;
                bfr[2 * p + 1][0] = q2; bfr[2 * p + 1][1] = q3;
            }
            int arow = wm * 32 + (lane & 15);
            int acol = k0 + ((lane >> 4) << 3);
            unsigned afr[2][4];
#pragma unroll
            for (int mt = 0; mt < 2; mt++)
                ldsm4(afr[mt][0], afr[mt][1], afr[mt][2], afr[mt][3],
                      Ah + (unsigned)((arow + mt * 16) * RT_STR + acol) * 2u);
#pragma unroll
            for (int mt = 0; mt < 2; mt++)
#pragma unroll
                for (int nt = 0; nt < 8; nt++)
                    mma16816(acc[mt][nt], afr[mt], bfr[nt][0], bfr[nt][1]);
#pragma unroll
            for (int mt = 0; mt < 2; mt++)
                ldsm4(afr[mt][0], afr[mt][1], afr[mt][2], afr[mt][3],
                      Al + (unsigned)((arow + mt * 16) * RT_STR + acol) * 2u);
#pragma unroll
            for (int mt = 0; mt < 2; mt++)
#pragma unroll
                for (int nt = 0; nt < 8; nt++)
                    mma16816(acc[mt][nt], afr[mt], bfr[nt][0], bfr[nt][1]);
        }
        __syncthreads();
    }

    // epilogue: smem transpose (fp32), add b_root, coalesced float4 stores
    float* trans = (float*)smem;   // [128][260] f32
#pragma unroll
    for (int mt = 0; mt < 2; mt++)
#pragma unroll
        for (int nt = 0; nt < 8; nt++) {
            int bl = wm * 32 + mt * 16 + (lane >> 2);
            int n = wn * 64 + nt * 8 + ((lane & 3) << 1);
            *(float2*)&trans[bl * 260 + n] = make_float2(acc[mt][nt][0], acc[mt][nt][1]);
            *(float2*)&trans[(bl + 8) * 260 + n] = make_float2(acc[mt][nt][2], acc[mt][nt][3]);
        }
    __syncthreads();
#pragma unroll
    for (int j = 0; j < 16; j++) {
        int f4 = tid + j * 512;          // float4 index over [128][64]
        int b = f4 >> 6, n4 = f4 & 63;
        float4 v = *(float4*)&trans[b * 260 + n4 * 4];
        float4 br = *(const float4*)&b_root[n4 * 4];
        v.x += br.x; v.y += br.y; v.z += br.z; v.w += br.w;
        *(float4*)&out[(b0 + b) * NOUT + n4 * 4] = v;
    }
}

// ---------------- launch ----------------
extern "C" void kernel_launch(void* const* d_in, const int* in_sizes, int n_in,
                              void* d_out, int out_size) {
    const float* x      = (const float*)d_in[0];
    const float* w_inp  = (const float*)d_in[1];
    const float* pbias  = (const float*)d_in[2];
    const float* W_mid  = (const float*)d_in[3];
    const float* b_mid  = (const float*)d_in[4];
    const float* W_root = (const float*)d_in[5];
    const float* b_root = (const float*)d_in[6];
    float* out = (float*)d_out;

    int batch = in_sizes[0] / INDIM;     // 16384
    int tiles = batch / 128;             // 128

    cudaFuncSetAttribute(k_mid,  cudaFuncAttributeMaxDynamicSharedMemorySize, MID_SMEM);
    cudaFuncSetAttribute(k_root, cudaFuncAttributeMaxDynamicSharedMemorySize, RT_SMEM);

    k_prep_mid<<<2048, 256>>>(w_inp, pbias, W_mid, b_mid);
    k_prep_root<<<2048, 256>>>(W_root);
    k_mid<<<dim3(tiles, NGRP), 256, MID_SMEM>>>(x);
    k_root<<<tiles, 512, RT_SMEM>>>(out, b_root);
}

// round 3
// speedup vs baseline: 1.1459x; 1.1459x over previous
#include <cuda_runtime.h>
#include <cuda_fp16.h>
#include <cstdint>

// ---------------- problem constants ----------------
#define INDIM 4096
#define NGRP  16
#define NOUT  256

// ---------------- device scratch ----------------
__device__ __half g_Wm[NGRP][128][256];   // folded mid weights [g][n][k]
__device__ float  g_cmid[NGRP][128];      // folded constants
__device__ __half g_Wr[NOUT][2048];       // root weights [n][k]

// ---------------- helpers ----------------
__device__ __forceinline__ unsigned smem_u32(const void* p) {
    unsigned a;
    asm("{ .reg .u64 t; cvta.to.shared.u64 t, %1; cvt.u32.u64 %0, t; }" : "=r"(a) : "l"(p));
    return a;
}
__device__ __forceinline__ void cp_async16(unsigned s, const void* g) {
    asm volatile("cp.async.cg.shared.global [%0], [%1], 16;" :: "r"(s), "l"(g));
}
#define CP_COMMIT() asm volatile("cp.async.commit_group;")
#define CP_WAIT0()  asm volatile("cp.async.wait_group 0;")
#define CP_WAIT1()  asm volatile("cp.async.wait_group 1;")
#define CP_WAIT2()  asm volatile("cp.async.wait_group 2;")

__device__ __forceinline__ void ldsm4(unsigned& r0, unsigned& r1, unsigned& r2, unsigned& r3,
                                      unsigned addr) {
    asm volatile("ldmatrix.sync.aligned.m8n8.x4.shared.b16 {%0,%1,%2,%3}, [%4];"
                 : "=r"(r0), "=r"(r1), "=r"(r2), "=r"(r3) : "r"(addr));
}
__device__ __forceinline__ void mma16816(float* c, const unsigned* a, unsigned b0, unsigned b1) {
    asm volatile(
        "mma.sync.aligned.m16n8k16.row.col.f32.f16.f16.f32 "
        "{%0,%1,%2,%3},{%4,%5,%6,%7},{%8,%9},{%0,%1,%2,%3};"
        : "+f"(c[0]), "+f"(c[1]), "+f"(c[2]), "+f"(c[3])
        : "r"(a[0]), "r"(a[1]), "r"(a[2]), "r"(a[3]), "r"(b0), "r"(b1));
}
__device__ __forceinline__ float fast_tanh(float v) {
    v = fminf(fmaxf(v, -15.f), 15.f);
    float e = __expf(2.f * v);
    return __fdividef(e - 1.f, e + 1.f);
}

// ---------------- prep ----------------
__global__ void k_prep_mid(const float* __restrict__ w_inp, const float* __restrict__ pbias,
                           const float* __restrict__ W_mid, const float* __restrict__ b_mid) {
    int g = blockIdx.x >> 7, n = blockIdx.x & 127, j = threadIdx.x;
    float wm = W_mid[(g * 256 + j) * 128 + n];
    g_Wm[g][n][j] = __float2half_rn(w_inp[g * 256 + j] * wm);
    __shared__ float red[256];
    red[j] = pbias[(g * 256 + j) >> 6] * wm;
    __syncthreads();
    for (int s = 128; s > 0; s >>= 1) {
        if (j < s) red[j] += red[j + s];
        __syncthreads();
    }
    if (j == 0) g_cmid[g][n] = red[0] + b_mid[g * 128 + n];
}
__global__ void k_prep_root(const float* __restrict__ W_root) {
    int idx = blockIdx.x * 256 + threadIdx.x;
    int k = idx >> 8, n = idx & 255;
    g_Wr[n][k] = __float2half_rn(W_root[idx]);
}

// ================= FUSED: 128 batch rows per CTA, 512 threads =================
// smem layout (bytes):
//   XS0 @ 0       : [128][68] f32  = 34816   x staging buf 0
//   XS1 @ 34816   : [128][68] f32  = 34816   x staging buf 1
//   WMS0 @ 69632  : [128][72] f16  = 18432   Wm chunk buf 0
//   WMS1 @ 88064  : [128][72] f16  = 18432   Wm chunk buf 1
//   XH  @ 106496  : [128][72] f16  = 18432   converted x chunk
//   PB  @ 124928  : [128][136] f16 = 34816   mid activations (root A)
//   WRB @ 159744  : [256][136] f16 = 69632   root weight slice for group g
#define XS0o   0u
#define XS1o   34816u
#define WMS0o  69632u
#define WMS1o  88064u
#define XHo    106496u
#define PBo    124928u
#define WRBo   159744u
#define SMEM_TOTAL 229376
#define XSTR 68
#define HSTR 72
#define PSTR 136

__global__ void __launch_bounds__(512, 1) k_fused(const float* __restrict__ x,
                                                  float* __restrict__ out,
                                                  const float* __restrict__ b_root) {
    extern __shared__ char smem[];
    unsigned sb = smem_u32(smem);
    const int tid = threadIdx.x, lane = tid & 31, wid = tid >> 5;
    const int wm = wid & 3, wn = wid >> 2;           // 4 M-warps x 4 N-warps
    const long long b0 = (long long)blockIdx.x * 128;

    float racc[2][8][4];                             // root acc: 128x256 / 512 thr
#pragma unroll
    for (int i = 0; i < 2; i++)
#pragma unroll
        for (int j = 0; j < 8; j++)
#pragma unroll
            for (int q = 0; q < 4; q++) racc[i][j][q] = 0.f;

// one commit group: x chunk [128,64] f32 + Wm chunk [128,64] f16
#define ISSUE_XWM(G, C)                                                          \
    do {                                                                         \
        unsigned xs = sb + (((C) & 1) ? XS1o : XS0o);                            \
        unsigned ws = sb + (((C) & 1) ? WMS1o : WMS0o);                          \
        int kg = (G) * 256 + (C) * 64;                                           \
        _Pragma("unroll") for (int j = 0; j < 4; j++) {                          \
            int idx = tid + j * 512;                                             \
            int r = idx >> 4, c4 = idx & 15;                                     \
            cp_async16(xs + (unsigned)(r * XSTR + c4 * 4) * 4u,                  \
                       x + (b0 + r) * INDIM + kg + c4 * 4);                      \
        }                                                                        \
        _Pragma("unroll") for (int j = 0; j < 2; j++) {                          \
            int idx = tid + j * 512;                                             \
            int n = idx >> 3, c8 = idx & 7;                                      \
            cp_async16(ws + (unsigned)(n * HSTR + c8 * 8) * 2u,                  \
                       &g_Wm[G][n][(C) * 64 + c8 * 8]);                          \
        }                                                                        \
        CP_COMMIT();                                                             \
    } while (0)

// one commit group: Wr slice [256 n, 128 k] f16
#define ISSUE_WR(G)                                                              \
    do {                                                                         \
        _Pragma("unroll") for (int j = 0; j < 8; j++) {                          \
            int idx = tid + j * 512;                                             \
            int n = idx >> 4, c16 = idx & 15;                                    \
            cp_async16(sb + WRBo + (unsigned)(n * PSTR + c16 * 8) * 2u,          \
                       &g_Wr[n][(G) * 128 + c16 * 8]);                           \
        }                                                                        \
        CP_COMMIT();                                                             \
    } while (0)

    ISSUE_XWM(0, 0);
    ISSUE_XWM(0, 1);

    for (int g = 0; g < NGRP; g++) {
        ISSUE_WR(g);

        float macc[2][4][4];                          // mid acc: 128x128 / 512 thr
#pragma unroll
        for (int i = 0; i < 2; i++)
#pragma unroll
            for (int j = 0; j < 4; j++)
#pragma unroll
                for (int q = 0; q < 4; q++) macc[i][j][q] = 0.f;

#pragma unroll
        for (int c = 0; c < 4; c++) {
            // wait for this chunk's x+Wm (commit-order: [kc_c, ..., possibly WR interleaved])
            if (c <= 1)      { CP_WAIT2(); }
            else if (c == 2) { CP_WAIT1(); }
            else             { if (g < NGRP - 1) CP_WAIT1(); else CP_WAIT0(); }
            __syncthreads();

            // convert x f32 -> f16 (each element touched once)
            const float* XSf = (const float*)(smem + ((c & 1) ? XS1o : XS0o));
#pragma unroll
            for (int j = 0; j < 8; j++) {
                int idx = tid + j * 512;
                int r = idx >> 5, c2 = (idx & 31) << 1;
                float2 v = *(const float2*)(XSf + r * XSTR + c2);
                *(__half2*)(smem + XHo + (unsigned)(r * HSTR + c2) * 2u) =
                    __floats2half2_rn(v.x, v.y);
            }
            __syncthreads();

            // mid MMA on this chunk (K=64)
            unsigned Xh = sb + XHo, WMS = sb + ((c & 1) ? WMS1o : WMS0o);
#pragma unroll
            for (int ks = 0; ks < 4; ks++) {
                int k0 = ks * 16;
                unsigned bfr[4][2];
#pragma unroll
                for (int p = 0; p < 2; p++) {
                    int grp = lane >> 3, r = lane & 7;
                    int n = wn * 32 + p * 16 + ((grp >> 1) << 3) + r;
                    int kk = k0 + ((grp & 1) << 3);
                    unsigned q0, q1, q2, q3;
                    ldsm4(q0, q1, q2, q3, WMS + (unsigned)(n * HSTR + kk) * 2u);
                    bfr[2 * p][0] = q0; bfr[2 * p][1] = q1;
                    bfr[2 * p + 1][0] = q2; bfr[2 * p + 1][1] = q3;
                }
                int arow = wm * 32 + (lane & 15);
                int acol = k0 + ((lane >> 4) << 3);
                unsigned afr[2][4];
#pragma unroll
                for (int mt = 0; mt < 2; mt++)
                    ldsm4(afr[mt][0], afr[mt][1], afr[mt][2], afr[mt][3],
                          Xh + (unsigned)((arow + mt * 16) * HSTR + acol) * 2u);
#pragma unroll
                for (int mt = 0; mt < 2; mt++)
#pragma unroll
                    for (int nt = 0; nt < 4; nt++)
                        mma16816(macc[mt][nt], afr[mt], bfr[nt][0], bfr[nt][1]);
            }

            if (c < 3) {
                __syncthreads();                       // all warps done with buffers
                if (c == 0)      ISSUE_XWM(g, 2);
                else if (c == 1) ISSUE_XWM(g, 3);
                else             { if (g < NGRP - 1) ISSUE_XWM(g + 1, 0); }
            }
        }

        // tanh -> P (fp16), coalesced-ish half2 writes
#pragma unroll
        for (int mt = 0; mt < 2; mt++)
#pragma unroll
            for (int nt = 0; nt < 4; nt++) {
                int bl = wm * 32 + mt * 16 + (lane >> 2);
                int n = wn * 32 + nt * 8 + ((lane & 3) << 1);
                float2 gc = *(const float2*)&g_cmid[g][n];
                *(__half2*)(smem + PBo + (unsigned)(bl * PSTR + n) * 2u) =
                    __floats2half2_rn(fast_tanh(macc[mt][nt][0] + gc.x),
                                      fast_tanh(macc[mt][nt][1] + gc.y));
                *(__half2*)(smem + PBo + (unsigned)((bl + 8) * PSTR + n) * 2u) =
                    __floats2half2_rn(fast_tanh(macc[mt][nt][2] + gc.x),
                                      fast_tanh(macc[mt][nt][3] + gc.y));
            }
        __syncthreads();                               // P visible; chunk-3 bufs free
        if (g < NGRP - 1) ISSUE_XWM(g + 1, 1);

        // root partial MMA: racc += P[128,128] @ WR[256,128]^T
        unsigned Pb = sb + PBo, Wr = sb + WRBo;
#pragma unroll
        for (int ks = 0; ks < 8; ks++) {
            int k0 = ks * 16;
            unsigned bfr[8][2];
#pragma unroll
            for (int p = 0; p < 4; p++) {
                int grp = lane >> 3, r = lane & 7;
                int n = wn * 64 + p * 16 + ((grp >> 1) << 3) + r;
                int kk = k0 + ((grp & 1) << 3);
                unsigned q0, q1, q2, q3;
                ldsm4(q0, q1, q2, q3, Wr + (unsigned)(n * PSTR + kk) * 2u);
                bfr[2 * p][0] = q0; bfr[2 * p][1] = q1;
                bfr[2 * p + 1][0] = q2; bfr[2 * p + 1][1] = q3;
            }
            int arow = wm * 32 + (lane & 15);
            int acol = k0 + ((lane >> 4) << 3);
            unsigned afr[2][4];
#pragma unroll
            for (int mt = 0; mt < 2; mt++)
                ldsm4(afr[mt][0], afr[mt][1], afr[mt][2], afr[mt][3],
                      Pb + (unsigned)((arow + mt * 16) * PSTR + acol) * 2u);
#pragma unroll
            for (int mt = 0; mt < 2; mt++)
#pragma unroll
                for (int nt = 0; nt < 8; nt++)
                    mma16816(racc[mt][nt], afr[mt], bfr[nt][0], bfr[nt][1]);
        }
        __syncthreads();                               // WR/P reads done before reuse
    }

    // epilogue: smem transpose, add b_root, coalesced float4 stores
    float* trans = (float*)smem;                       // [128][260] f32
#pragma unroll
    for (int mt = 0; mt < 2; mt++)
#pragma unroll
        for (int nt = 0; nt < 8; nt++) {
            int bl = wm * 32 + mt * 16 + (lane >> 2);
            int n = wn * 64 + nt * 8 + ((lane & 3) << 1);
            *(float2*)&trans[bl * 260 + n] = make_float2(racc[mt][nt][0], racc[mt][nt][1]);
            *(float2*)&trans[(bl + 8) * 260 + n] = make_float2(racc[mt][nt][2], racc[mt][nt][3]);
        }
    __syncthreads();
#pragma unroll
    for (int j = 0; j < 16; j++) {
        int f4 = tid + j * 512;
        int b = f4 >> 6, n4 = f4 & 63;
        float4 v = *(float4*)&trans[b * 260 + n4 * 4];
        float4 br = *(const float4*)&b_root[n4 * 4];
        v.x += br.x; v.y += br.y; v.z += br.z; v.w += br.w;
        *(float4*)&out[(b0 + b) * NOUT + n4 * 4] = v;
    }
}

// ---------------- launch ----------------
extern "C" void kernel_launch(void* const* d_in, const int* in_sizes, int n_in,
                              void* d_out, int out_size) {
    const float* x      = (const float*)d_in[0];
    const float* w_inp  = (const float*)d_in[1];
    const float* pbias  = (const float*)d_in[2];
    const float* W_mid  = (const float*)d_in[3];
    const float* b_mid  = (const float*)d_in[4];
    const float* W_root = (const float*)d_in[5];
    const float* b_root = (const float*)d_in[6];
    float* out = (float*)d_out;

    int batch = in_sizes[0] / INDIM;   // 16384
    int tiles = batch / 128;           // 128 CTAs

    cudaFuncSetAttribute(k_fused, cudaFuncAttributeMaxDynamicSharedMemorySize, SMEM_TOTAL);

    k_prep_mid<<<2048, 256>>>(w_inp, pbias, W_mid, b_mid);
    k_prep_root<<<2048, 256>>>(W_root);
    k_fused<<<tiles, 512, SMEM_TOTAL>>>(x, out, b_root);
}